// round 16
// baseline (speedup 1.0000x reference)
#include <cuda_runtime.h>
#include <cuda_fp16.h>
#include <cstdint>

#define HH 384
#define WW 384
#define BATCH 4
#define CIN 64
#define COUT 64
#define NPIX (BATCH*HH*WW)

// ---------------------------------------------------------------------------
// Scratch: A operand pre-baked as half2 in mma.m16n8k16 A-fragment order.
// u32 index = (((tap*4 + kc)*8 + ct)*32 + lane)*4 + j
//   row v = ct*16 + (lane>>2) + 8*(j&1)
//   k pair = (lane&3)*2 + 8*(j>>1) + {0,1};  ci = kc*16 + k
//   rows v<64 (ct 0..3): W_low_eff(co=v);  v>=64 (ct 4..7): W_high(co=v-64)
// ---------------------------------------------------------------------------
__device__ uint32_t g_ahalf[9 * 4096];
__device__ unsigned char g_flags[NPIX];

__device__ __forceinline__ uint32_t smem_u32(const void* p) {
    uint32_t a;
    asm("{ .reg .u64 t; cvta.to.shared.u64 t, %1; cvt.u32.u64 %0, t; }"
        : "=r"(a) : "l"(p));
    return a;
}

__device__ __forceinline__ void mma_f16(float* d, const uint32_t* a,
                                        const uint32_t* b) {
    asm volatile(
        "mma.sync.aligned.m16n8k16.row.col.f32.f16.f16.f32 "
        "{%0,%1,%2,%3}, {%4,%5,%6,%7}, {%8,%9}, {%0,%1,%2,%3};"
        : "+f"(d[0]), "+f"(d[1]), "+f"(d[2]), "+f"(d[3])
        : "r"(a[0]), "r"(a[1]), "r"(a[2]), "r"(a[3]), "r"(b[0]), "r"(b[1]));
}

#define CP_ASYNC16(dst_u32, src_ptr) \
    asm volatile("cp.async.cg.shared.global [%0], [%1], 16;" \
                 :: "r"(dst_u32), "l"(src_ptr))
#define CP_COMMIT()  asm volatile("cp.async.commit_group;" ::: "memory")
#define CP_WAIT0()   asm volatile("cp.async.wait_group 0;" ::: "memory")

// ---------------------------------------------------------------------------
// Prep 1: weights -> fp16 fragment-ordered A images. (unchanged from R15)
// ---------------------------------------------------------------------------
__global__ void prep_weights_f16(const float* __restrict__ high_w,  // (64,64,3,3)
                                 const float* __restrict__ low1_w,  // (16,64,3,3)
                                 const float* __restrict__ low2_w)  // (64,16,1,1)
{
    int id = blockIdx.x * blockDim.x + threadIdx.x;
    if (id >= 9 * 4096) return;
    int j    = id & 3;
    int lane = (id >> 2) & 31;
    int ct   = (id >> 7) & 7;
    int kc   = (id >> 10) & 3;
    int tap  = id >> 12;
    int v  = ct * 16 + (lane >> 2) + 8 * (j & 1);
    int kb = (lane & 3) * 2 + 8 * (j >> 1);
    float w01[2];
#pragma unroll
    for (int e = 0; e < 2; e++) {
        int ci = kc * 16 + kb + e;
        if (v < 64) {
            float wle = 0.0f;
#pragma unroll
            for (int m = 0; m < 16; m++)
                wle += low2_w[v * 16 + m] * low1_w[(m * 64 + ci) * 9 + tap];
            w01[e] = wle;
        } else {
            w01[e] = high_w[((v - 64) * 64 + ci) * 9 + tap];
        }
    }
    __half2 h = __floats2half2_rn(w01[0], w01[1]);
    g_ahalf[id] = *(const uint32_t*)&h;
}

__global__ void prep_flags(const int* __restrict__ mask_idx,
                           const int* __restrict__ inv_idx)
{
    int i = blockIdx.x * blockDim.x + threadIdx.x;
    if (i >= NPIX) return;
    if (i < NPIX / 2) g_flags[mask_idx[i]] = 1;
    else              g_flags[inv_idx[i - NPIX / 2]] = 0;
}

// ---------------------------------------------------------------------------
// Main: 128-pixel strip; pixels compacted by route flag so every n-tile is
// path-pure -> only the needed 64 couts per pixel are computed.
// 8 warps; warp w owns n-tiles {w, w+8, w+16} (<= 3), 4 co-tiles each.
// smem: [perm 544][whi 16][pad][A0 16K][A1 16K][cache2 32x136][obuf 64x132]
// ---------------------------------------------------------------------------
#define OFF_PERM  0
#define OFF_WHI   544
#define OFF_A0    1024
#define OFF_A1    (1024 + 16384)
#define OFF_CH    (1024 + 32768)
#define OFF_OUT   (OFF_CH + 32*136*4)
#define SMEM_TOTAL (OFF_OUT + 64*132*4)   // 84992

__global__ __launch_bounds__(256, 2)
void conv_mma(const float* __restrict__ x, float* __restrict__ out)
{
    extern __shared__ char smem[];
    int* perm = (int*)(smem + OFF_PERM);                // [136] slot -> pixel
    int* whi  = (int*)(smem + OFF_WHI);                 // [4] per-warp high cnt
    uint32_t* cache2 = (uint32_t*)(smem + OFF_CH);      // [32][136] half2 pairs
    float* obuf = (float*)(smem + OFF_OUT);             // [64][132]
    const uint32_t sbase = smem_u32(smem);

    const int tid  = threadIdx.x;
    const int wrp  = tid >> 5;
    const int lane = tid & 31;

    const int idx = blockIdx.x;
    const int b   = idx / 1152;
    const int rem = idx % 1152;
    const int h   = rem / 3;
    const int w0  = (rem % 3) * 128;

    // ---- compaction phase 1: ballot counts ----
    int f = 0;
    unsigned bal = 0;
    if (tid < 136) perm[tid] = 132;          // pad sentinel (zero cache col)
    if (tid < 128) {
        f = g_flags[(b * HH + h) * WW + w0 + tid];
        bal = __ballot_sync(0xffffffffu, f);
        if (lane == 0) whi[wrp] = __popc(bal);
    }

    // prologue: prefetch A[tap 0] (16 KB)
    {
        const char* src = (const char*)g_ahalf;
        uint32_t dst = sbase + OFF_A0 + tid * 16;
#pragma unroll
        for (int i = 0; i < 4; i++)
            CP_ASYNC16(dst + i * 4096, src + tid * 16 + i * 4096);
        CP_COMMIT();
    }
    __syncthreads();

    // ---- compaction phase 2: scatter perm ----
    const int nh = whi[0] + whi[1] + whi[2] + whi[3];
    const int Th = (nh + 7) >> 3;            // high n-tiles
    const int Sl = Th * 8;                   // low list start slot
    const int T  = Th + ((128 - nh + 7) >> 3);
    if (tid < 128) {
        int hib = __popc(bal & ((1u << lane) - 1));
        int hcum = 0;
#pragma unroll
        for (int q = 0; q < 4; q++) if (q < wrp) hcum += whi[q];
        int pos = f ? (hcum + hib)
                    : (Sl + (wrp * 32 - hcum) + (lane - hib));
        perm[pos] = tid;
    }
    __syncthreads();

    // ---- per-warp tile setup (perm static across taps) ----
    int myT = 0;
    int mycol[3];   // per-lane cache column (pixel) for slot t*8 + (lane>>2)
    int mybase[3];  // A ct base: high tiles -> rows 64.. (ct 4..7)
#pragma unroll
    for (int q = 0; q < 3; q++) {
        int t = wrp + q * 8;
        if (t < T) {
            mycol[q]  = perm[t * 8 + (lane >> 2)];
            mybase[q] = (t < Th) ? 4 : 0;
            myT = q + 1;
        } else { mycol[q] = 132; mybase[q] = 0; }
    }

    float d[3][4][4];
#pragma unroll
    for (int q = 0; q < 3; q++)
#pragma unroll
        for (int ct = 0; ct < 4; ct++)
#pragma unroll
            for (int i = 0; i < 4; i++) d[q][ct][i] = 0.0f;

    for (int kh = 0; kh < 3; kh++) {
        __syncthreads();                 // prior taps' cache reads complete
        const int rin = h + kh - 1;
        const bool rok = (rin >= 0 && rin < HH);
        for (int i = tid; i < 32 * 136; i += 256) {
            int cp = i / 136, cc = i % 136;
            int g = w0 - 1 + cc;
            float v0 = 0.0f, v1 = 0.0f;
            if (rok && g >= 0 && g < WW && cc < 130) {
                const float* base = x + ((b * CIN + cp * 2) * HH + rin) * WW + g;
                v0 = base[0];
                v1 = base[HH * WW];
            }
            __half2 hv = __floats2half2_rn(v0, v1);
            cache2[i] = *(const uint32_t*)&hv;
        }

        for (int kw = 0; kw < 3; kw++) {
            const int tap = kh * 3 + kw;
            CP_WAIT0();
            __syncthreads();
            if (tap < 8) {
                const char* src = (const char*)(g_ahalf + (tap + 1) * 4096);
                uint32_t dst = sbase + (((tap + 1) & 1) ? OFF_A1 : OFF_A0)
                             + tid * 16;
#pragma unroll
                for (int i = 0; i < 4; i++)
                    CP_ASYNC16(dst + i * 4096, src + tid * 16 + i * 4096);
                CP_COMMIT();
            }
            const uint4* As = (const uint4*)(smem + ((tap & 1) ? OFF_A1 : OFF_A0));

            const int tg = lane & 3;
#pragma unroll
            for (int kc = 0; kc < 4; kc++) {
                const int cp0 = kc * 8 + tg;
#pragma unroll
                for (int q = 0; q < 3; q++) {
                    if (q < myT) {
                        uint32_t bb[2];
                        bb[0] = cache2[cp0 * 136 + mycol[q] + kw];
                        bb[1] = cache2[(cp0 + 4) * 136 + mycol[q] + kw];
#pragma unroll
                        for (int ctl = 0; ctl < 4; ctl++) {
                            uint4 af = As[(kc * 8 + mybase[q] + ctl) * 32 + lane];
                            mma_f16(d[q][ctl], (const uint32_t*)&af, bb);
                        }
                    }
                }
            }
        }
    }
    __syncthreads();                     // mainloop cache reads done

    // epilogue: scatter through perm — every value computed is used.
    const int r4 = lane >> 2;
    const int c2 = (lane & 3) * 2;
#pragma unroll
    for (int q = 0; q < 3; q++) {
        if (q < myT) {
            int t = wrp + q * 8;
            int s0 = t * 8 + c2;
            int px0 = perm[s0], px1 = perm[s0 + 1];
#pragma unroll
            for (int ctl = 0; ctl < 4; ctl++) {
#pragma unroll
                for (int half = 0; half < 2; half++) {
                    const int co = ctl * 16 + r4 + half * 8;
                    if (px0 < 128) obuf[co * 132 + px0] = d[q][ctl][half * 2];
                    if (px1 < 128) obuf[co * 132 + px1] = d[q][ctl][half * 2 + 1];
                }
            }
        }
    }
    __syncthreads();

    // coalesced store: thread -> (co = tid>>2, quarter = tid&3), 32 floats
    {
        const int co = tid >> 2, qq = tid & 3;
        float* orow = out + ((b * COUT + co) * HH + h) * WW + w0 + qq * 32;
        const float* srow = obuf + co * 132 + qq * 32;
#pragma unroll
        for (int v = 0; v < 8; v++)
            *(float4*)(orow + v * 4) = *(const float4*)(srow + v * 4);
    }
}

// ---------------------------------------------------------------------------
extern "C" void kernel_launch(void* const* d_in, const int* in_sizes, int n_in,
                              void* d_out, int out_size)
{
    const float* x      = (const float*)d_in[0];
    const float* high_w = (const float*)d_in[1];
    const float* low1_w = (const float*)d_in[2];
    const float* low2_w = (const float*)d_in[3];
    const int* mask_idx = (const int*)d_in[4];
    const int* inv_idx  = (const int*)d_in[5];
    float* out = (float*)d_out;

    cudaFuncSetAttribute(conv_mma, cudaFuncAttributeMaxDynamicSharedMemorySize,
                         SMEM_TOTAL);

    prep_weights_f16<<<(9 * 4096 + 255) / 256, 256>>>(high_w, low1_w, low2_w);
    prep_flags<<<(NPIX + 255) / 256, 256>>>(mask_idx, inv_idx);
    conv_mma<<<4608, 256, SMEM_TOTAL>>>(x, out);
}

// round 17
// speedup vs baseline: 1.8083x; 1.8083x over previous
#include <cuda_runtime.h>
#include <cuda_fp16.h>
#include <cstdint>

#define HH 384
#define WW 384
#define BATCH 4
#define CIN 64
#define COUT 64
#define NPIX (BATCH*HH*WW)

// ---------------------------------------------------------------------------
// Scratch:
// g_ahalf: mainloop A operand, half2, m16n8k16 fragment order.
//   u32 index = (((tap*4 + kc)*5 + ct)*32 + lane)*4 + j
//   ct 0..3: rows = high couts (co = ct*16 + r);  ct 4: rows = mid channels
//   row r = (lane>>2) + 8*(j&1);  ci = kc*16 + (lane&3)*2 + 8*(j>>1) + e
// g_aexp: expand A operand (low2, 64co x 16k), fragment order, 512 u32.
// ---------------------------------------------------------------------------
__device__ uint32_t g_ahalf[9 * 2560];
__device__ uint32_t g_aexp[512];
__device__ unsigned char g_flags[NPIX];

__device__ __forceinline__ uint32_t smem_u32(const void* p) {
    uint32_t a;
    asm("{ .reg .u64 t; cvta.to.shared.u64 t, %1; cvt.u32.u64 %0, t; }"
        : "=r"(a) : "l"(p));
    return a;
}

__device__ __forceinline__ void mma_f16(float* d, const uint32_t* a,
                                        const uint32_t* b) {
    asm volatile(
        "mma.sync.aligned.m16n8k16.row.col.f32.f16.f16.f32 "
        "{%0,%1,%2,%3}, {%4,%5,%6,%7}, {%8,%9}, {%0,%1,%2,%3};"
        : "+f"(d[0]), "+f"(d[1]), "+f"(d[2]), "+f"(d[3])
        : "r"(a[0]), "r"(a[1]), "r"(a[2]), "r"(a[3]), "r"(b[0]), "r"(b[1]));
}

#define CP_ASYNC16(dst_u32, src_ptr) \
    asm volatile("cp.async.cg.shared.global [%0], [%1], 16;" \
                 :: "r"(dst_u32), "l"(src_ptr))
#define CP_COMMIT()  asm volatile("cp.async.commit_group;" ::: "memory")
#define CP_WAIT0()   asm volatile("cp.async.wait_group 0;" ::: "memory")

// ---------------------------------------------------------------------------
// Prep 1: bake mainloop A (high rows + mid rows) and expand A (low2).
// ---------------------------------------------------------------------------
__global__ void prep_weights(const float* __restrict__ high_w,  // (64,64,3,3)
                             const float* __restrict__ low1_w,  // (16,64,3,3)
                             const float* __restrict__ low2_w)  // (64,16,1,1)
{
    int id = blockIdx.x * blockDim.x + threadIdx.x;
    if (id < 9 * 2560) {
        int j    = id & 3;
        int lane = (id >> 2) & 31;
        int rest = id >> 7;
        int ct   = rest % 5;
        int rest2 = rest / 5;
        int kc   = rest2 & 3;
        int tap  = rest2 >> 2;
        int r  = (lane >> 2) + 8 * (j & 1);
        int kb = (lane & 3) * 2 + 8 * (j >> 1);
        float w01[2];
#pragma unroll
        for (int e = 0; e < 2; e++) {
            int ci = kc * 16 + kb + e;
            if (ct < 4)
                w01[e] = high_w[(((ct * 16 + r) * 64) + ci) * 9 + tap];
            else
                w01[e] = low1_w[(r * 64 + ci) * 9 + tap];
        }
        __half2 h = __floats2half2_rn(w01[0], w01[1]);
        g_ahalf[id] = *(const uint32_t*)&h;
    } else if (id < 9 * 2560 + 512) {
        int e2   = id - 9 * 2560;
        int j    = e2 & 3;
        int lane = (e2 >> 2) & 31;
        int ct   = (e2 >> 7) & 3;
        int co = ct * 16 + (lane >> 2) + 8 * (j & 1);
        int k0 = (lane & 3) * 2 + 8 * (j >> 1);
        __half2 h = __floats2half2_rn(low2_w[co * 16 + k0],
                                      low2_w[co * 16 + k0 + 1]);
        g_aexp[e2] = *(const uint32_t*)&h;
    }
}

__global__ void prep_flags(const int* __restrict__ mask_idx,
                           const int* __restrict__ inv_idx)
{
    int i = blockIdx.x * blockDim.x + threadIdx.x;
    if (i >= NPIX) return;
    if (i < NPIX / 2) g_flags[mask_idx[i]] = 1;
    else              g_flags[inv_idx[i - NPIX / 2]] = 0;
}

// ---------------------------------------------------------------------------
// Main: 128-pixel strip; mainloop computes 80 rows (64 high couts + 16 mid),
// then a single K=16 mma pass expands mid -> 64 low couts; per-pixel select.
// 8 warps; warp p owns pixels [p*16, p*16+16) = 2 n-tiles, all 5 co-tiles.
// smem: [flags 128][A0 10240][A1 10240][cache2 32x136 u32 / midh 128x20 half]
//       [obuf 64x132 f32]
// ---------------------------------------------------------------------------
#define OFF_FLAGS 0
#define OFF_A0    128
#define OFF_A1    (128 + 10240)
#define OFF_CH    (128 + 20480)
#define OFF_OUT   (OFF_CH + 32*136*4)
#define SMEM_TOTAL (OFF_OUT + 64*132*4)   // 71808

__global__ __launch_bounds__(256, 2)
void conv_mma(const float* __restrict__ x, float* __restrict__ out)
{
    extern __shared__ char smem[];
    unsigned char* flg = (unsigned char*)(smem + OFF_FLAGS);
    uint32_t* cache2 = (uint32_t*)(smem + OFF_CH);   // [32][136] half2 (ci,ci+1)
    __half* midh = (__half*)(smem + OFF_CH);         // [128][20] after mainloop
    float* obuf = (float*)(smem + OFF_OUT);          // [64][132]
    const uint32_t sbase = smem_u32(smem);

    const int tid  = threadIdx.x;
    const int p    = tid >> 5;       // warp: pixel group of 16
    const int lane = tid & 31;

    const int idx = blockIdx.x;
    const int b   = idx / 1152;
    const int rem = idx % 1152;
    const int h   = rem / 3;
    const int w0  = (rem % 3) * 128;

    if (tid < 128) flg[tid] = g_flags[(b * HH + h) * WW + w0 + tid];

    // prologue: prefetch A[tap 0] (10240 B = 640 float4)
    {
        const char* src = (const char*)g_ahalf;
        uint32_t dst = sbase + OFF_A0;
#pragma unroll
        for (int i = 0; i < 3; i++) {
            int e = tid + i * 256;
            if (e < 640) CP_ASYNC16(dst + e * 16, src + e * 16);
        }
        CP_COMMIT();
    }

    float d[5][2][4];
#pragma unroll
    for (int ct = 0; ct < 5; ct++)
#pragma unroll
        for (int nt = 0; nt < 2; nt++)
#pragma unroll
            for (int i = 0; i < 4; i++) d[ct][nt][i] = 0.0f;

    for (int kh = 0; kh < 3; kh++) {
        __syncthreads();                 // prior taps' cache reads complete
        const int rin = h + kh - 1;
        const bool rok = (rin >= 0 && rin < HH);
        for (int i = tid; i < 32 * 136; i += 256) {
            int cp = i / 136, cc = i % 136;
            int g = w0 - 1 + cc;
            float v0 = 0.0f, v1 = 0.0f;
            if (rok && g >= 0 && g < WW && cc < 130) {
                const float* base = x + ((b * CIN + cp * 2) * HH + rin) * WW + g;
                v0 = base[0];
                v1 = base[HH * WW];
            }
            __half2 hv = __floats2half2_rn(v0, v1);
            cache2[i] = *(const uint32_t*)&hv;
        }

        for (int kw = 0; kw < 3; kw++) {
            const int tap = kh * 3 + kw;
            CP_WAIT0();                  // A[tap] landed
            __syncthreads();             // visibility + old-buffer reads done
            if (tap < 8) {               // prefetch A[tap+1]
                const char* src = (const char*)(g_ahalf + (tap + 1) * 2560);
                uint32_t dst = sbase + (((tap + 1) & 1) ? OFF_A1 : OFF_A0);
#pragma unroll
                for (int i = 0; i < 3; i++) {
                    int e = tid + i * 256;
                    if (e < 640) CP_ASYNC16(dst + e * 16, src + e * 16);
                }
                CP_COMMIT();
            }
            const uint4* As = (const uint4*)(smem + ((tap & 1) ? OFF_A1 : OFF_A0));

            const int nb0 = p * 16 + (lane >> 2) + kw;   // cache col, nt=0
            const int tg  = lane & 3;
#pragma unroll
            for (int kc = 0; kc < 4; kc++) {
                const int cp0 = kc * 8 + tg;
                uint32_t bf[2][2];
#pragma unroll
                for (int nt = 0; nt < 2; nt++) {
                    bf[nt][0] = cache2[cp0 * 136 + nb0 + nt * 8];
                    bf[nt][1] = cache2[(cp0 + 4) * 136 + nb0 + nt * 8];
                }
#pragma unroll
                for (int ct = 0; ct < 5; ct++) {
                    uint4 af = As[(kc * 5 + ct) * 32 + lane];
                    const uint32_t* a = (const uint32_t*)&af;
                    mma_f16(d[ct][0], a, bf[0]);
                    mma_f16(d[ct][1], a, bf[1]);
                }
            }
        }
    }
    __syncthreads();                     // mainloop cache reads done

    // ---- stage mid channels (ct=4 fragments) into midh[n][m] as fp16 ----
#pragma unroll
    for (int nt = 0; nt < 2; nt++) {
#pragma unroll
        for (int jj = 0; jj < 4; jj++) {
            int m = (lane >> 2) + 8 * (jj >> 1);
            int n = p * 16 + nt * 8 + (lane & 3) * 2 + (jj & 1);
            midh[n * 20 + m] = __float2half(d[4][nt][jj]);
        }
    }
    __syncthreads();

    // ---- expand mid -> 64 low couts (K=16, one chunk) + select + obuf ----
    {
        uint4 ae[4];
#pragma unroll
        for (int ct = 0; ct < 4; ct++)
            ae[ct] = ((const uint4*)g_aexp)[ct * 32 + lane];

        const int r4 = lane >> 2;
        const int c2 = (lane & 3) * 2;
        const int k0 = c2;               // b-frag k pair base
#pragma unroll
        for (int nt = 0; nt < 2; nt++) {
            const int nb = p * 16 + nt * 8 + r4;   // b-frag column
            uint32_t bx[2];
            bx[0] = *(const uint32_t*)&midh[nb * 20 + k0];
            bx[1] = *(const uint32_t*)&midh[nb * 20 + k0 + 8];
            const int n0 = p * 16 + nt * 8 + c2;
            const bool f0 = flg[n0] != 0;
            const bool f1 = flg[n0 + 1] != 0;
#pragma unroll
            for (int ct = 0; ct < 4; ct++) {
                float de[4] = {0.f, 0.f, 0.f, 0.f};
                mma_f16(de, (const uint32_t*)&ae[ct], bx);
#pragma unroll
                for (int half = 0; half < 2; half++) {
                    const int co = ct * 16 + r4 + half * 8;
                    obuf[co * 132 + n0]     = f0 ? d[ct][nt][half * 2]
                                                 : de[half * 2];
                    obuf[co * 132 + n0 + 1] = f1 ? d[ct][nt][half * 2 + 1]
                                                 : de[half * 2 + 1];
                }
            }
        }
    }
    __syncthreads();

    // coalesced store: thread -> (co = tid>>2, quarter = tid&3), 32 floats
    {
        const int co = tid >> 2, qq = tid & 3;
        float* orow = out + ((b * COUT + co) * HH + h) * WW + w0 + qq * 32;
        const float* srow = obuf + co * 132 + qq * 32;
#pragma unroll
        for (int v = 0; v < 8; v++)
            *(float4*)(orow + v * 4) = *(const float4*)(srow + v * 4);
    }
}

// ---------------------------------------------------------------------------
extern "C" void kernel_launch(void* const* d_in, const int* in_sizes, int n_in,
                              void* d_out, int out_size)
{
    const float* x      = (const float*)d_in[0];
    const float* high_w = (const float*)d_in[1];
    const float* low1_w = (const float*)d_in[2];
    const float* low2_w = (const float*)d_in[3];
    const int* mask_idx = (const int*)d_in[4];
    const int* inv_idx  = (const int*)d_in[5];
    float* out = (float*)d_out;

    cudaFuncSetAttribute(conv_mma, cudaFuncAttributeMaxDynamicSharedMemorySize,
                         SMEM_TOTAL);

    prep_weights<<<(9 * 2560 + 512 + 255) / 256, 256>>>(high_w, low1_w, low2_w);
    prep_flags<<<(NPIX + 255) / 256, 256>>>(mask_idx, inv_idx);
    conv_mma<<<4608, 256, SMEM_TOTAL>>>(x, out);
}